// round 1
// baseline (speedup 1.0000x reference)
#include <cuda_runtime.h>
#include <math.h>

#define D 512
#define NMAX 20000
#define EMAX 320000

// ---------------- scratch (device globals: allocation-free) ----------------
__device__ float g_t[NMAX * D];      // tangent vectors (logmap0(x))
__device__ float g_q[NMAX * D];      // q ; later reused as h = attn @ Wo^T + bo
__device__ float g_k[NMAX * D];
__device__ float g_v[NMAX * D];
__device__ float g_attn[NMAX * D];
__device__ float g_scores[EMAX];     // scores, then exp(score - m)
__device__ int   g_cnt[NMAX];
__device__ int   g_off[NMAX + 1];
__device__ int   g_cur[NMAX];
__device__ int   g_eid[EMAX];

// ---------------- logmap0 ----------------
__global__ void logmap_kernel(const float* __restrict__ x, int n) {
    int row = blockIdx.x;
    if (row >= n) return;
    const float* xr = x + (size_t)row * D;
    float ss = 0.f;
    for (int i = threadIdx.x; i < D; i += 128) { float v = xr[i]; ss += v * v; }
    for (int o = 16; o > 0; o >>= 1) ss += __shfl_down_sync(0xffffffffu, ss, o);
    __shared__ float sred[4];
    int lane = threadIdx.x & 31, w = threadIdx.x >> 5;
    if (lane == 0) sred[w] = ss;
    __syncthreads();
    float tot = sred[0] + sred[1] + sred[2] + sred[3];
    float nrm = sqrtf(tot);
    float nc = fminf(fmaxf(nrm, 1e-7f), 1.f - 1e-6f);
    float fac = atanhf(nc) / nc;
    for (int i = threadIdx.x; i < D; i += 128)
        g_t[(size_t)row * D + i] = fac * xr[i];
}

// ---------------- expmap0 (reads g_q as h, writes final output) ----------------
__global__ void expmap_kernel(float* __restrict__ out, int n) {
    int row = blockIdx.x;
    if (row >= n) return;
    const float* hr = g_q + (size_t)row * D;
    float ss = 0.f;
    for (int i = threadIdx.x; i < D; i += 128) { float v = hr[i]; ss += v * v; }
    for (int o = 16; o > 0; o >>= 1) ss += __shfl_down_sync(0xffffffffu, ss, o);
    __shared__ float sred[4];
    int lane = threadIdx.x & 31, w = threadIdx.x >> 5;
    if (lane == 0) sred[w] = ss;
    __syncthreads();
    float tot = sred[0] + sred[1] + sred[2] + sred[3];
    float nrm = sqrtf(tot);
    float nc = fmaxf(nrm, 1e-7f);
    float fac = tanhf(nc) / nc;
    for (int i = threadIdx.x; i < D; i += 128)
        out[(size_t)row * D + i] = fac * hr[i];
}

// ---------------- SGEMM: C[M,512] = A[M,512] @ W[512,512]^T (+bias)*scale ----
// sel: 0 -> A=g_t, C=g_q   1 -> A=g_t, C=g_k   2 -> A=g_t, C=g_v
//      3 -> A=g_attn, C=g_q (reuse as h)
__global__ __launch_bounds__(256, 2)
void sgemm_kernel(const float* __restrict__ W, const float* __restrict__ bias,
                  int sel, int M, float scale) {
    const float* __restrict__ A = (sel == 3) ? g_attn : g_t;
    float* __restrict__ C = (sel == 1) ? g_k : (sel == 2) ? g_v : g_q;

    __shared__ float As[16][128];
    __shared__ float Ws[16][128];
    int bm = blockIdx.y * 128, bn = blockIdx.x * 128;
    int tid = threadIdx.x;
    int lr = tid >> 2;            // 0..63
    int lc = (tid & 3) * 4;       // 0,4,8,12
    int ty = tid >> 4, tx = tid & 15;

    float acc[8][8];
#pragma unroll
    for (int i = 0; i < 8; i++)
#pragma unroll
        for (int j = 0; j < 8; j++) acc[i][j] = 0.f;

    for (int k0 = 0; k0 < 512; k0 += 16) {
#pragma unroll
        for (int h = 0; h < 2; h++) {
            int row = bm + lr + h * 64;
            float4 va = make_float4(0.f, 0.f, 0.f, 0.f);
            if (row < M) va = *(const float4*)(A + (size_t)row * 512 + k0 + lc);
            As[lc + 0][lr + h * 64] = va.x;
            As[lc + 1][lr + h * 64] = va.y;
            As[lc + 2][lr + h * 64] = va.z;
            As[lc + 3][lr + h * 64] = va.w;
            int wrow = bn + lr + h * 64;  // always < 512
            float4 vw = *(const float4*)(W + (size_t)wrow * 512 + k0 + lc);
            Ws[lc + 0][lr + h * 64] = vw.x;
            Ws[lc + 1][lr + h * 64] = vw.y;
            Ws[lc + 2][lr + h * 64] = vw.z;
            Ws[lc + 3][lr + h * 64] = vw.w;
        }
        __syncthreads();
#pragma unroll
        for (int kk = 0; kk < 16; kk++) {
            float4 a0 = *(const float4*)&As[kk][ty * 4];
            float4 a1 = *(const float4*)&As[kk][64 + ty * 4];
            float4 w0 = *(const float4*)&Ws[kk][tx * 4];
            float4 w1 = *(const float4*)&Ws[kk][64 + tx * 4];
            float ra[8] = {a0.x, a0.y, a0.z, a0.w, a1.x, a1.y, a1.z, a1.w};
            float rw[8] = {w0.x, w0.y, w0.z, w0.w, w1.x, w1.y, w1.z, w1.w};
#pragma unroll
            for (int i = 0; i < 8; i++)
#pragma unroll
                for (int j = 0; j < 8; j++) acc[i][j] += ra[i] * rw[j];
        }
        __syncthreads();
    }

#pragma unroll
    for (int i = 0; i < 8; i++) {
        int row = bm + ty * 4 + (i & 3) + (i >> 2) * 64;
        if (row >= M) continue;
#pragma unroll
        for (int j = 0; j < 8; j++) {
            int col = bn + tx * 4 + (j & 3) + (j >> 2) * 64;
            C[(size_t)row * 512 + col] = (acc[i][j] + bias[col]) * scale;
        }
    }
}

// ---------------- CSR build (by dst) ----------------
__global__ void zero_cnt_kernel(int n) {
    int i = blockIdx.x * blockDim.x + threadIdx.x;
    if (i < n) g_cnt[i] = 0;
}
__global__ void hist_kernel(const int* __restrict__ dst, int E) {
    int i = blockIdx.x * blockDim.x + threadIdx.x;
    if (i < E) atomicAdd(&g_cnt[dst[i]], 1);
}
__global__ void scan_kernel(int n) {
    __shared__ int sdata[1024];
    __shared__ int carry_s;
    int t = threadIdx.x;
    if (t == 0) carry_s = 0;
    __syncthreads();
    for (int base = 0; base < n; base += 1024) {
        int idx = base + t;
        int v = (idx < n) ? g_cnt[idx] : 0;
        sdata[t] = v;
        __syncthreads();
        for (int off = 1; off < 1024; off <<= 1) {
            int tmp = (t >= off) ? sdata[t - off] : 0;
            __syncthreads();
            sdata[t] += tmp;
            __syncthreads();
        }
        int incl = sdata[t];
        int carry = carry_s;
        if (idx < n) {
            int excl = carry + incl - v;
            g_off[idx] = excl;
            g_cur[idx] = excl;
        }
        __syncthreads();
        if (t == 1023) carry_s = carry + incl;
        __syncthreads();
    }
    if (t == 0) g_off[n] = carry_s;
}
__global__ void scatter_kernel(const int* __restrict__ dst, int E) {
    int i = blockIdx.x * blockDim.x + threadIdx.x;
    if (i < E) {
        int p = atomicAdd(&g_cur[dst[i]], 1);
        g_eid[p] = i;
    }
}

// ---------------- fused per-dst attention (scores + softmax + aggregate) ----
__global__ void attn_kernel(const int* __restrict__ srcArr, int n) {
    int dnode = blockIdx.x;
    if (dnode >= n) return;
    int beg = g_off[dnode], end = g_off[dnode + 1];
    __shared__ float qs[D];
    __shared__ float sred[4];
    __shared__ float s_m, s_inv;
    int tid = threadIdx.x, lane = tid & 31, w = tid >> 5;

    const float* qr = g_q + (size_t)dnode * D;
    for (int i = tid; i < D; i += 128) qs[i] = qr[i];
    __syncthreads();

    // pass 1: scores + block max (warp per edge)
    float wmax = -3.4e38f;
    for (int e = beg + w; e < end; e += 4) {
        int s = srcArr[g_eid[e]];
        const float* kr = g_k + (size_t)s * D;
        float acc = 0.f;
#pragma unroll
        for (int i = 0; i < D / 32; i++)
            acc += qs[lane + i * 32] * kr[lane + i * 32];
        for (int o = 16; o > 0; o >>= 1) acc += __shfl_down_sync(0xffffffffu, acc, o);
        if (lane == 0) {
            g_scores[e] = acc;
            wmax = fmaxf(wmax, acc);
        }
    }
    if (lane == 0) sred[w] = wmax;
    __syncthreads();
    if (tid == 0)
        s_m = fmaxf(fmaxf(sred[0], sred[1]), fmaxf(sred[2], sred[3]));
    __syncthreads();
    float m = s_m;

    // pass 2: exp + denom
    float ds = 0.f;
    for (int e = beg + tid; e < end; e += 128) {
        float ex = expf(g_scores[e] - m);
        g_scores[e] = ex;
        ds += ex;
    }
    for (int o = 16; o > 0; o >>= 1) ds += __shfl_down_sync(0xffffffffu, ds, o);
    __syncthreads();   // sred reuse barrier
    if (lane == 0) sred[w] = ds;
    __syncthreads();
    if (tid == 0) s_inv = 1.f / (sred[0] + sred[1] + sred[2] + sred[3]);
    __syncthreads();
    float inv = s_inv;

    // pass 3: attn[dst] = sum alpha * v[src]  (thread owns 4 columns)
    float a0 = 0.f, a1 = 0.f, a2 = 0.f, a3 = 0.f;
    for (int e = beg; e < end; e++) {
        int s = srcArr[g_eid[e]];
        float al = g_scores[e] * inv;
        const float* vr = g_v + (size_t)s * D;
        a0 += al * vr[tid];
        a1 += al * vr[tid + 128];
        a2 += al * vr[tid + 256];
        a3 += al * vr[tid + 384];
    }
    float* ar = g_attn + (size_t)dnode * D;
    ar[tid] = a0;
    ar[tid + 128] = a1;
    ar[tid + 256] = a2;
    ar[tid + 384] = a3;
}

// ---------------- launch ----------------
extern "C" void kernel_launch(void* const* d_in, const int* in_sizes, int n_in,
                              void* d_out, int out_size) {
    const float* x  = (const float*)d_in[0];
    const int*   src = (const int*)d_in[1];
    const int*   dst = (const int*)d_in[2];
    const float* Wq = (const float*)d_in[3];
    const float* bq = (const float*)d_in[4];
    const float* Wk = (const float*)d_in[5];
    const float* bk = (const float*)d_in[6];
    const float* Wv = (const float*)d_in[7];
    const float* bv = (const float*)d_in[8];
    const float* Wo = (const float*)d_in[9];
    const float* bo = (const float*)d_in[10];
    float* out = (float*)d_out;

    int n = in_sizes[0] / D;
    int E = in_sizes[1];
    float scale = 1.f / sqrtf((float)D);

    logmap_kernel<<<n, 128>>>(x, n);

    dim3 gg(4, (n + 127) / 128);
    sgemm_kernel<<<gg, 256>>>(Wq, bq, 0, n, scale);
    sgemm_kernel<<<gg, 256>>>(Wk, bk, 1, n, 1.f);
    sgemm_kernel<<<gg, 256>>>(Wv, bv, 2, n, 1.f);

    zero_cnt_kernel<<<(n + 255) / 256, 256>>>(n);
    hist_kernel<<<(E + 255) / 256, 256>>>(dst, E);
    scan_kernel<<<1, 1024>>>(n);
    scatter_kernel<<<(E + 255) / 256, 256>>>(dst, E);

    attn_kernel<<<n, 128>>>(src, n);

    sgemm_kernel<<<gg, 256>>>(Wo, bo, 3, n, 1.f);
    expmap_kernel<<<n, 128>>>(out, n);
}

// round 2
// speedup vs baseline: 1.2614x; 1.2614x over previous
#include <cuda_runtime.h>
#include <math.h>
#include <stdint.h>

#define D 512
#define NMAX 20000
#define EMAX 320000

// ---------------- scratch (device globals: allocation-free) ----------------
__device__ float g_t[NMAX * D];      // tangent vectors (logmap0(x))
__device__ float g_q[NMAX * D];      // q ; later reused as h = attn @ Wo^T + bo
__device__ float g_k[NMAX * D];
__device__ float g_v[NMAX * D];
__device__ float g_attn[NMAX * D];
__device__ float g_scores[EMAX];     // scores, then exp(score - m)
__device__ int   g_cnt[NMAX];
__device__ int   g_off[NMAX + 1];
__device__ int   g_cur[NMAX];
__device__ int   g_eid[EMAX];

// ---------------- logmap0 ----------------
__global__ void logmap_kernel(const float* __restrict__ x, int n) {
    int row = blockIdx.x;
    if (row >= n) return;
    const float* xr = x + (size_t)row * D;
    float ss = 0.f;
    for (int i = threadIdx.x; i < D; i += 128) { float v = xr[i]; ss += v * v; }
    for (int o = 16; o > 0; o >>= 1) ss += __shfl_down_sync(0xffffffffu, ss, o);
    __shared__ float sred[4];
    int lane = threadIdx.x & 31, w = threadIdx.x >> 5;
    if (lane == 0) sred[w] = ss;
    __syncthreads();
    float tot = sred[0] + sred[1] + sred[2] + sred[3];
    float nrm = sqrtf(tot);
    float nc = fminf(fmaxf(nrm, 1e-7f), 1.f - 1e-6f);
    float fac = atanhf(nc) / nc;
    for (int i = threadIdx.x; i < D; i += 128)
        g_t[(size_t)row * D + i] = fac * xr[i];
}

// ---------------- expmap0 (reads g_q as h, writes final output) ------------
__global__ void expmap_kernel(float* __restrict__ out, int n) {
    int row = blockIdx.x;
    if (row >= n) return;
    const float* hr = g_q + (size_t)row * D;
    float ss = 0.f;
    for (int i = threadIdx.x; i < D; i += 128) { float v = hr[i]; ss += v * v; }
    for (int o = 16; o > 0; o >>= 1) ss += __shfl_down_sync(0xffffffffu, ss, o);
    __shared__ float sred[4];
    int lane = threadIdx.x & 31, w = threadIdx.x >> 5;
    if (lane == 0) sred[w] = ss;
    __syncthreads();
    float tot = sred[0] + sred[1] + sred[2] + sred[3];
    float nrm = sqrtf(tot);
    float nc = fmaxf(nrm, 1e-7f);
    float fac = tanhf(nc) / nc;
    for (int i = threadIdx.x; i < D; i += 128)
        out[(size_t)row * D + i] = fac * hr[i];
}

// ---------------- tf32 round helper ----------------------------------------
__device__ __forceinline__ float f2tf32(float x) {
    uint32_t u;
    asm("cvt.rna.tf32.f32 %0, %1;" : "=r"(u) : "f"(x));
    return __uint_as_float(u);
}

// ---------------- TF32 tensor-core GEMM:
//   C[M,512] = (A[M,512] @ W[512,512]^T + bias) * scale
// sel: 0 -> A=g_t, C=g_q   1 -> A=g_t, C=g_k   2 -> A=g_t, C=g_v
//      3 -> A=g_attn, C=g_q (reuse as h)
// Block tile 128x128x32, 8 warps (2m x 4n), warp tile 64x32,
// micro tiles m16n8k8 (4 x 4 per warp per k-step of 8).
__global__ __launch_bounds__(256, 2)
void tgemm_kernel(const float* __restrict__ W, const float* __restrict__ bias,
                  int sel, int M, float scale) {
    const float* __restrict__ A = (sel == 3) ? g_attn : g_t;
    float* __restrict__ C = (sel == 1) ? g_k : (sel == 2) ? g_v : g_q;

    __shared__ float As[128][40];   // [m][k], pad stride 40 -> float4-aligned
    __shared__ float Ws[128][40];   // [n][k]

    int bm = blockIdx.y * 128, bn = blockIdx.x * 128;
    int tid = threadIdx.x;
    int lane = tid & 31, warp = tid >> 5;
    int wm = (warp >> 2) * 64;      // 2 warps across m
    int wn = (warp & 3) * 32;       // 4 warps across n
    int g = lane >> 2, tg = lane & 3;

    float acc[4][4][4];
#pragma unroll
    for (int mt = 0; mt < 4; mt++)
#pragma unroll
        for (int nt = 0; nt < 4; nt++)
#pragma unroll
            for (int i = 0; i < 4; i++) acc[mt][nt][i] = 0.f;

    int lrow = tid >> 3, lcol = (tid & 7) << 2;

    for (int k0 = 0; k0 < 512; k0 += 32) {
#pragma unroll
        for (int i = 0; i < 4; i++) {
            int row = lrow + i * 32;
            int ga = bm + row;
            float4 va = make_float4(0.f, 0.f, 0.f, 0.f);
            if (ga < M) va = *(const float4*)(A + (size_t)ga * 512 + k0 + lcol);
            As[row][lcol + 0] = f2tf32(va.x);
            As[row][lcol + 1] = f2tf32(va.y);
            As[row][lcol + 2] = f2tf32(va.z);
            As[row][lcol + 3] = f2tf32(va.w);
            float4 vw = *(const float4*)(W + (size_t)(bn + row) * 512 + k0 + lcol);
            Ws[row][lcol + 0] = f2tf32(vw.x);
            Ws[row][lcol + 1] = f2tf32(vw.y);
            Ws[row][lcol + 2] = f2tf32(vw.z);
            Ws[row][lcol + 3] = f2tf32(vw.w);
        }
        __syncthreads();

#pragma unroll
        for (int ks = 0; ks < 4; ks++) {
            int kb = ks * 8;
            uint32_t af[4][4], bf[4][2];
#pragma unroll
            for (int mt = 0; mt < 4; mt++) {
                int r = wm + mt * 16 + g;
                af[mt][0] = __float_as_uint(As[r][kb + tg]);
                af[mt][1] = __float_as_uint(As[r + 8][kb + tg]);
                af[mt][2] = __float_as_uint(As[r][kb + tg + 4]);
                af[mt][3] = __float_as_uint(As[r + 8][kb + tg + 4]);
            }
#pragma unroll
            for (int nt = 0; nt < 4; nt++) {
                int r = wn + nt * 8 + g;
                bf[nt][0] = __float_as_uint(Ws[r][kb + tg]);
                bf[nt][1] = __float_as_uint(Ws[r][kb + tg + 4]);
            }
#pragma unroll
            for (int mt = 0; mt < 4; mt++)
#pragma unroll
                for (int nt = 0; nt < 4; nt++) {
                    asm volatile(
                        "mma.sync.aligned.m16n8k8.row.col.f32.tf32.tf32.f32 "
                        "{%0,%1,%2,%3}, {%4,%5,%6,%7}, {%8,%9}, {%0,%1,%2,%3};"
                        : "+f"(acc[mt][nt][0]), "+f"(acc[mt][nt][1]),
                          "+f"(acc[mt][nt][2]), "+f"(acc[mt][nt][3])
                        : "r"(af[mt][0]), "r"(af[mt][1]),
                          "r"(af[mt][2]), "r"(af[mt][3]),
                          "r"(bf[nt][0]), "r"(bf[nt][1]));
                }
        }
        __syncthreads();
    }

    // epilogue: c0/c1 -> (row, col..col+1), c2/c3 -> (row+8, col..col+1)
#pragma unroll
    for (int mt = 0; mt < 4; mt++) {
        int row0 = bm + wm + mt * 16 + g;
#pragma unroll
        for (int nt = 0; nt < 4; nt++) {
            int col = bn + wn + nt * 8 + tg * 2;
            float b0v = bias[col], b1v = bias[col + 1];
            if (row0 < M) {
                float2 o;
                o.x = (acc[mt][nt][0] + b0v) * scale;
                o.y = (acc[mt][nt][1] + b1v) * scale;
                *(float2*)(C + (size_t)row0 * 512 + col) = o;
            }
            if (row0 + 8 < M) {
                float2 o;
                o.x = (acc[mt][nt][2] + b0v) * scale;
                o.y = (acc[mt][nt][3] + b1v) * scale;
                *(float2*)(C + (size_t)(row0 + 8) * 512 + col) = o;
            }
        }
    }
}

// ---------------- CSR build (by dst) ----------------
__global__ void zero_cnt_kernel(int n) {
    int i = blockIdx.x * blockDim.x + threadIdx.x;
    if (i < n) g_cnt[i] = 0;
}
__global__ void hist_kernel(const int* __restrict__ dst, int E) {
    int i = blockIdx.x * blockDim.x + threadIdx.x;
    if (i < E) atomicAdd(&g_cnt[dst[i]], 1);
}
__global__ void scan_kernel(int n) {
    __shared__ int sdata[1024];
    __shared__ int carry_s;
    int t = threadIdx.x;
    if (t == 0) carry_s = 0;
    __syncthreads();
    for (int base = 0; base < n; base += 1024) {
        int idx = base + t;
        int v = (idx < n) ? g_cnt[idx] : 0;
        sdata[t] = v;
        __syncthreads();
        for (int off = 1; off < 1024; off <<= 1) {
            int tmp = (t >= off) ? sdata[t - off] : 0;
            __syncthreads();
            sdata[t] += tmp;
            __syncthreads();
        }
        int incl = sdata[t];
        int carry = carry_s;
        if (idx < n) {
            int excl = carry + incl - v;
            g_off[idx] = excl;
            g_cur[idx] = excl;
        }
        __syncthreads();
        if (t == 1023) carry_s = carry + incl;
        __syncthreads();
    }
    if (t == 0) g_off[n] = carry_s;
}
__global__ void scatter_kernel(const int* __restrict__ dst, int E) {
    int i = blockIdx.x * blockDim.x + threadIdx.x;
    if (i < E) {
        int p = atomicAdd(&g_cur[dst[i]], 1);
        g_eid[p] = i;
    }
}

// ---------------- fused per-dst attention (scores + softmax + aggregate) ----
__global__ void attn_kernel(const int* __restrict__ srcArr, int n) {
    int dnode = blockIdx.x;
    if (dnode >= n) return;
    int beg = g_off[dnode], end = g_off[dnode + 1];
    __shared__ float qs[D];
    __shared__ float sred[4];
    __shared__ float s_m, s_inv;
    int tid = threadIdx.x, lane = tid & 31, w = tid >> 5;

    const float* qr = g_q + (size_t)dnode * D;
    for (int i = tid; i < D; i += 128) qs[i] = qr[i];
    __syncthreads();

    // pass 1: scores + block max (warp per edge)
    float wmax = -3.4e38f;
    for (int e = beg + w; e < end; e += 4) {
        int s = srcArr[g_eid[e]];
        const float* kr = g_k + (size_t)s * D;
        float acc = 0.f;
#pragma unroll
        for (int i = 0; i < D / 32; i++)
            acc += qs[lane + i * 32] * kr[lane + i * 32];
        for (int o = 16; o > 0; o >>= 1) acc += __shfl_down_sync(0xffffffffu, acc, o);
        if (lane == 0) {
            g_scores[e] = acc;
            wmax = fmaxf(wmax, acc);
        }
    }
    if (lane == 0) sred[w] = wmax;
    __syncthreads();
    if (tid == 0)
        s_m = fmaxf(fmaxf(sred[0], sred[1]), fmaxf(sred[2], sred[3]));
    __syncthreads();
    float m = s_m;

    // pass 2: exp + denom
    float ds = 0.f;
    for (int e = beg + tid; e < end; e += 128) {
        float ex = expf(g_scores[e] - m);
        g_scores[e] = ex;
        ds += ex;
    }
    for (int o = 16; o > 0; o >>= 1) ds += __shfl_down_sync(0xffffffffu, ds, o);
    __syncthreads();   // sred reuse barrier
    if (lane == 0) sred[w] = ds;
    __syncthreads();
    if (tid == 0) s_inv = 1.f / (sred[0] + sred[1] + sred[2] + sred[3]);
    __syncthreads();
    float inv = s_inv;

    // pass 3: attn[dst] = sum alpha * v[src]  (thread owns 4 columns)
    float a0 = 0.f, a1 = 0.f, a2 = 0.f, a3 = 0.f;
    for (int e = beg; e < end; e++) {
        int s = srcArr[g_eid[e]];
        float al = g_scores[e] * inv;
        const float* vr = g_v + (size_t)s * D;
        a0 += al * vr[tid];
        a1 += al * vr[tid + 128];
        a2 += al * vr[tid + 256];
        a3 += al * vr[tid + 384];
    }
    float* ar = g_attn + (size_t)dnode * D;
    ar[tid] = a0;
    ar[tid + 128] = a1;
    ar[tid + 256] = a2;
    ar[tid + 384] = a3;
}

// ---------------- launch ----------------
extern "C" void kernel_launch(void* const* d_in, const int* in_sizes, int n_in,
                              void* d_out, int out_size) {
    const float* x  = (const float*)d_in[0];
    const int*   src = (const int*)d_in[1];
    const int*   dst = (const int*)d_in[2];
    const float* Wq = (const float*)d_in[3];
    const float* bq = (const float*)d_in[4];
    const float* Wk = (const float*)d_in[5];
    const float* bk = (const float*)d_in[6];
    const float* Wv = (const float*)d_in[7];
    const float* bv = (const float*)d_in[8];
    const float* Wo = (const float*)d_in[9];
    const float* bo = (const float*)d_in[10];
    float* out = (float*)d_out;

    int n = in_sizes[0] / D;
    int E = in_sizes[1];
    float scale = 1.f / sqrtf((float)D);

    logmap_kernel<<<n, 128>>>(x, n);

    dim3 gg(4, (n + 127) / 128);
    tgemm_kernel<<<gg, 256>>>(Wq, bq, 0, n, scale);
    tgemm_kernel<<<gg, 256>>>(Wk, bk, 1, n, 1.f);
    tgemm_kernel<<<gg, 256>>>(Wv, bv, 2, n, 1.f);

    zero_cnt_kernel<<<(n + 255) / 256, 256>>>(n);
    hist_kernel<<<(E + 255) / 256, 256>>>(dst, E);
    scan_kernel<<<1, 1024>>>(n);
    scatter_kernel<<<(E + 255) / 256, 256>>>(dst, E);

    attn_kernel<<<n, 128>>>(src, n);

    tgemm_kernel<<<gg, 256>>>(Wo, bo, 3, n, 1.f);
    expmap_kernel<<<n, 128>>>(out, n);
}

// round 5
// speedup vs baseline: 2.8313x; 2.2446x over previous
#include <cuda_runtime.h>
#include <math.h>
#include <stdint.h>

#define D 512
#define NMAX 20000
#define EMAX 320000

// ---------------- scratch (device globals: allocation-free) ----------------
__device__ float g_t[NMAX * D];      // tangent vectors, tf32-rounded
__device__ float g_q[NMAX * D];      // q ; later reused as h
__device__ float g_k[NMAX * D];
__device__ float g_v[NMAX * D];
__device__ float g_attn[NMAX * D];   // tf32-rounded at write
__device__ float g_Wc[4 * D * D];    // tf32-rounded weight copies (q,k,v,o)
__device__ float g_scores[EMAX];
__device__ int   g_cnt[NMAX];
__device__ int   g_off[NMAX + 1];
__device__ int   g_cur[NMAX];
__device__ int   g_eid[EMAX];

__device__ __forceinline__ float f2tf32(float x) {
    uint32_t u;
    asm("cvt.rna.tf32.f32 %0, %1;" : "=r"(u) : "f"(x));
    return __uint_as_float(u);
}

__device__ __forceinline__ void cp_async16(void* sptr, const void* gptr, bool pred) {
    uint32_t sa = (uint32_t)__cvta_generic_to_shared(sptr);
    int sz = pred ? 16 : 0;
    asm volatile("cp.async.cg.shared.global [%0], [%1], 16, %2;\n"
                 :: "r"(sa), "l"(gptr), "r"(sz));
}

// ---------------- W conversion (tf32 round, once per call) -----------------
__global__ void convw_kernel(const float* __restrict__ Wq, const float* __restrict__ Wk,
                             const float* __restrict__ Wv, const float* __restrict__ Wo) {
    int i = blockIdx.x * blockDim.x + threadIdx.x;   // float4 index
    int total = 4 * D * D / 4;
    if (i >= total) return;
    int which = i / (D * D / 4);
    int off = i - which * (D * D / 4);
    const float* src = (which == 0) ? Wq : (which == 1) ? Wk : (which == 2) ? Wv : Wo;
    float4 v = ((const float4*)src)[off];
    v.x = f2tf32(v.x); v.y = f2tf32(v.y); v.z = f2tf32(v.z); v.w = f2tf32(v.w);
    ((float4*)g_Wc)[i] = v;
}

// ---------------- logmap0 (writes tf32-rounded tangent) --------------------
__global__ void logmap_kernel(const float* __restrict__ x, int n) {
    int row = blockIdx.x;
    if (row >= n) return;
    const float4* xr = (const float4*)(x + (size_t)row * D);
    float4 xv = xr[threadIdx.x];
    float ss = xv.x * xv.x + xv.y * xv.y + xv.z * xv.z + xv.w * xv.w;
    for (int o = 16; o > 0; o >>= 1) ss += __shfl_down_sync(0xffffffffu, ss, o);
    __shared__ float sred[4];
    int lane = threadIdx.x & 31, w = threadIdx.x >> 5;
    if (lane == 0) sred[w] = ss;
    __syncthreads();
    float tot = sred[0] + sred[1] + sred[2] + sred[3];
    float nrm = sqrtf(tot);
    float nc = fminf(fmaxf(nrm, 1e-7f), 1.f - 1e-6f);
    float fac = atanhf(nc) / nc;
    float4 o4;
    o4.x = f2tf32(fac * xv.x); o4.y = f2tf32(fac * xv.y);
    o4.z = f2tf32(fac * xv.z); o4.w = f2tf32(fac * xv.w);
    ((float4*)(g_t + (size_t)row * D))[threadIdx.x] = o4;
}

// ---------------- expmap0 (reads g_q as h, writes output) ------------------
__global__ void expmap_kernel(float* __restrict__ out, int n) {
    int row = blockIdx.x;
    if (row >= n) return;
    const float4* hr = (const float4*)(g_q + (size_t)row * D);
    float4 hv = hr[threadIdx.x];
    float ss = hv.x * hv.x + hv.y * hv.y + hv.z * hv.z + hv.w * hv.w;
    for (int o = 16; o > 0; o >>= 1) ss += __shfl_down_sync(0xffffffffu, ss, o);
    __shared__ float sred[4];
    int lane = threadIdx.x & 31, w = threadIdx.x >> 5;
    if (lane == 0) sred[w] = ss;
    __syncthreads();
    float tot = sred[0] + sred[1] + sred[2] + sred[3];
    float nrm = sqrtf(tot);
    float nc = fmaxf(nrm, 1e-7f);
    float fac = tanhf(nc) / nc;
    float4 o4;
    o4.x = fac * hv.x; o4.y = fac * hv.y; o4.z = fac * hv.z; o4.w = fac * hv.w;
    ((float4*)(out + (size_t)row * D))[threadIdx.x] = o4;
}

// ---------------- TF32 tensor-core GEMM (cp.async double-buffered) ---------
//   C[M,512] = (A[M,512] @ W[512,512]^T + bias) * scale
// sel = sel_base + blockIdx.z : 0->q 1->k 2->v (A=g_t), 3->h (A=g_attn, C=g_q)
#define SM_STRIDE 40
#define TILE_FLOATS (128 * SM_STRIDE)
#define GEMM_SMEM (4 * TILE_FLOATS * 4)   // 2 bufs x (A+W) x 128x40 floats

__global__ __launch_bounds__(256, 2)
void tgemm_kernel(const float* __restrict__ b0, const float* __restrict__ b1,
                  const float* __restrict__ b2, int sel_base, int M, float qscale) {
    extern __shared__ float smem[];
    int sel = sel_base + blockIdx.z;
    const float* __restrict__ A = (sel == 3) ? g_attn : g_t;
    const float* __restrict__ W = g_Wc + (size_t)sel * D * D;
    float* __restrict__ C = (sel == 1) ? g_k : (sel == 2) ? g_v : g_q;
    const float* __restrict__ bias = (blockIdx.z == 0) ? b0 : (blockIdx.z == 1) ? b1 : b2;
    float scale = (sel == 0) ? qscale : 1.f;

    int bm = blockIdx.y * 128, bn = blockIdx.x * 128;
    int tid = threadIdx.x;
    int lane = tid & 31, warp = tid >> 5;
    int wm = (warp >> 2) * 64;
    int wn = (warp & 3) * 32;
    int g = lane >> 2, tg = lane & 3;
    int lrow = tid >> 3, lcol = (tid & 7) << 2;

    float acc[4][4][4];
#pragma unroll
    for (int mt = 0; mt < 4; mt++)
#pragma unroll
        for (int nt = 0; nt < 4; nt++)
#pragma unroll
            for (int i = 0; i < 4; i++) acc[mt][nt][i] = 0.f;

    // prefetch helper (tile index it: k0 = it*32, buffer it&1)
    auto prefetch = [&](int it) {
        float* As = smem + (it & 1) * 2 * TILE_FLOATS;
        float* Ws = As + TILE_FLOATS;
        int k0 = it * 32;
#pragma unroll
        for (int i = 0; i < 4; i++) {
            int row = lrow + i * 32;
            int ga = bm + row;
            cp_async16(&As[row * SM_STRIDE + lcol],
                       A + (size_t)ga * D + k0 + lcol, ga < M);
            cp_async16(&Ws[row * SM_STRIDE + lcol],
                       W + (size_t)(bn + row) * D + k0 + lcol, true);
        }
        asm volatile("cp.async.commit_group;\n" ::);
    };

    prefetch(0);

    for (int it = 0; it < 16; it++) {
        // Issue next tile FIRST so wait_group 1 guarantees tile `it` landed
        // (oldest of the two in-flight groups). Buffer overwrite safety:
        // prefetch(it+1) writes buf (it+1)&1, whose compute finished in
        // iteration it-1 and was fenced by that iteration's trailing
        // __syncthreads().
        if (it + 1 < 16) {
            prefetch(it + 1);
            asm volatile("cp.async.wait_group 1;\n" ::);
        } else {
            asm volatile("cp.async.wait_group 0;\n" ::);
        }
        __syncthreads();

        const float* As = smem + (it & 1) * 2 * TILE_FLOATS;
        const float* Ws = As + TILE_FLOATS;

#pragma unroll
        for (int ks = 0; ks < 4; ks++) {
            int kb = ks * 8;
            uint32_t af[4][4], bf[4][2];
#pragma unroll
            for (int mt = 0; mt < 4; mt++) {
                int r = wm + mt * 16 + g;
                af[mt][0] = __float_as_uint(As[r * SM_STRIDE + kb + tg]);
                af[mt][1] = __float_as_uint(As[(r + 8) * SM_STRIDE + kb + tg]);
                af[mt][2] = __float_as_uint(As[r * SM_STRIDE + kb + tg + 4]);
                af[mt][3] = __float_as_uint(As[(r + 8) * SM_STRIDE + kb + tg + 4]);
            }
#pragma unroll
            for (int nt = 0; nt < 4; nt++) {
                int r = wn + nt * 8 + g;
                bf[nt][0] = __float_as_uint(Ws[r * SM_STRIDE + kb + tg]);
                bf[nt][1] = __float_as_uint(Ws[r * SM_STRIDE + kb + tg + 4]);
            }
#pragma unroll
            for (int mt = 0; mt < 4; mt++)
#pragma unroll
                for (int nt = 0; nt < 4; nt++) {
                    asm volatile(
                        "mma.sync.aligned.m16n8k8.row.col.f32.tf32.tf32.f32 "
                        "{%0,%1,%2,%3}, {%4,%5,%6,%7}, {%8,%9}, {%0,%1,%2,%3};"
                        : "+f"(acc[mt][nt][0]), "+f"(acc[mt][nt][1]),
                          "+f"(acc[mt][nt][2]), "+f"(acc[mt][nt][3])
                        : "r"(af[mt][0]), "r"(af[mt][1]),
                          "r"(af[mt][2]), "r"(af[mt][3]),
                          "r"(bf[nt][0]), "r"(bf[nt][1]));
                }
        }
        __syncthreads();
    }

#pragma unroll
    for (int mt = 0; mt < 4; mt++) {
        int row0 = bm + wm + mt * 16 + g;
#pragma unroll
        for (int nt = 0; nt < 4; nt++) {
            int col = bn + wn + nt * 8 + tg * 2;
            float b0v = bias[col], b1v = bias[col + 1];
            if (row0 < M) {
                float2 o;
                o.x = (acc[mt][nt][0] + b0v) * scale;
                o.y = (acc[mt][nt][1] + b1v) * scale;
                *(float2*)(C + (size_t)row0 * D + col) = o;
            }
            if (row0 + 8 < M) {
                float2 o;
                o.x = (acc[mt][nt][2] + b0v) * scale;
                o.y = (acc[mt][nt][3] + b1v) * scale;
                *(float2*)(C + (size_t)(row0 + 8) * D + col) = o;
            }
        }
    }
}

// ---------------- CSR build (by dst) ----------------
__global__ void zero_cnt_kernel(int n) {
    int i = blockIdx.x * blockDim.x + threadIdx.x;
    if (i < n) g_cnt[i] = 0;
}
__global__ void hist_kernel(const int* __restrict__ dst, int E) {
    int i = blockIdx.x * blockDim.x + threadIdx.x;
    if (i < E) atomicAdd(&g_cnt[dst[i]], 1);
}
__global__ void scan_kernel(int n) {
    __shared__ int sdata[1024];
    __shared__ int carry_s;
    int t = threadIdx.x;
    if (t == 0) carry_s = 0;
    __syncthreads();
    for (int base = 0; base < n; base += 1024) {
        int idx = base + t;
        int v = (idx < n) ? g_cnt[idx] : 0;
        sdata[t] = v;
        __syncthreads();
        for (int off = 1; off < 1024; off <<= 1) {
            int tmp = (t >= off) ? sdata[t - off] : 0;
            __syncthreads();
            sdata[t] += tmp;
            __syncthreads();
        }
        int incl = sdata[t];
        int carry = carry_s;
        if (idx < n) {
            int excl = carry + incl - v;
            g_off[idx] = excl;
            g_cur[idx] = excl;
        }
        __syncthreads();
        if (t == 1023) carry_s = carry + incl;
        __syncthreads();
    }
    if (t == 0) g_off[n] = carry_s;
}
__global__ void scatter_kernel(const int* __restrict__ dst, int E) {
    int i = blockIdx.x * blockDim.x + threadIdx.x;
    if (i < E) {
        int p = atomicAdd(&g_cur[dst[i]], 1);
        g_eid[p] = i;
    }
}

// ---------------- fused per-dst attention ----------------------------------
__global__ void attn_kernel(const int* __restrict__ srcArr, int n) {
    int dnode = blockIdx.x;
    if (dnode >= n) return;
    int beg = g_off[dnode], end = g_off[dnode + 1];
    __shared__ float4 qs[D / 4];
    __shared__ float sred[4];
    __shared__ float s_m, s_inv;
    int tid = threadIdx.x, lane = tid & 31, w = tid >> 5;

    qs[tid] = ((const float4*)(g_q + (size_t)dnode * D))[tid];
    __syncthreads();

    // pass 1: scores + block max (warp per edge, float4 dots)
    float wmax = -3.4e38f;
    for (int e = beg + w; e < end; e += 4) {
        int s = srcArr[g_eid[e]];
        const float4* kr = (const float4*)(g_k + (size_t)s * D);
        float acc = 0.f;
#pragma unroll
        for (int i = 0; i < 4; i++) {
            float4 kv = kr[lane + 32 * i];
            float4 qv = qs[lane + 32 * i];
            acc += kv.x * qv.x + kv.y * qv.y + kv.z * qv.z + kv.w * qv.w;
        }
        for (int o = 16; o > 0; o >>= 1) acc += __shfl_down_sync(0xffffffffu, acc, o);
        if (lane == 0) {
            g_scores[e] = acc;
            wmax = fmaxf(wmax, acc);
        }
    }
    if (lane == 0) sred[w] = wmax;
    __syncthreads();
    if (tid == 0)
        s_m = fmaxf(fmaxf(sred[0], sred[1]), fmaxf(sred[2], sred[3]));
    __syncthreads();
    float m = s_m;

    // pass 2: exp + denom
    float ds = 0.f;
    for (int e = beg + tid; e < end; e += 128) {
        float ex = expf(g_scores[e] - m);
        g_scores[e] = ex;
        ds += ex;
    }
    for (int o = 16; o > 0; o >>= 1) ds += __shfl_down_sync(0xffffffffu, ds, o);
    __syncthreads();
    if (lane == 0) sred[w] = ds;
    __syncthreads();
    if (tid == 0) s_inv = 1.f / (sred[0] + sred[1] + sred[2] + sred[3]);
    __syncthreads();
    float inv = s_inv;

    // pass 3: thread owns 4 contiguous cols; one LDG.128 per edge
    float4 a = make_float4(0.f, 0.f, 0.f, 0.f);
    for (int e = beg; e < end; e++) {
        int s = srcArr[g_eid[e]];
        float al = g_scores[e] * inv;
        float4 v4 = ((const float4*)(g_v + (size_t)s * D))[tid];
        a.x += al * v4.x; a.y += al * v4.y;
        a.z += al * v4.z; a.w += al * v4.w;
    }
    float4 o4;
    o4.x = f2tf32(a.x); o4.y = f2tf32(a.y);
    o4.z = f2tf32(a.z); o4.w = f2tf32(a.w);
    ((float4*)(g_attn + (size_t)dnode * D))[tid] = o4;
}

// ---------------- launch ----------------
extern "C" void kernel_launch(void* const* d_in, const int* in_sizes, int n_in,
                              void* d_out, int out_size) {
    const float* x  = (const float*)d_in[0];
    const int*   src = (const int*)d_in[1];
    const int*   dst = (const int*)d_in[2];
    const float* Wq = (const float*)d_in[3];
    const float* bq = (const float*)d_in[4];
    const float* Wk = (const float*)d_in[5];
    const float* bk = (const float*)d_in[6];
    const float* Wv = (const float*)d_in[7];
    const float* bv = (const float*)d_in[8];
    const float* Wo = (const float*)d_in[9];
    const float* bo = (const float*)d_in[10];
    float* out = (float*)d_out;

    int n = in_sizes[0] / D;
    int E = in_sizes[1];
    float qscale = 1.f / sqrtf((float)D);

    cudaFuncSetAttribute(tgemm_kernel,
                         cudaFuncAttributeMaxDynamicSharedMemorySize, GEMM_SMEM);

    convw_kernel<<<(4 * D * D / 4 + 255) / 256, 256>>>(Wq, Wk, Wv, Wo);
    logmap_kernel<<<n, 128>>>(x, n);

    dim3 gqkv(4, (n + 127) / 128, 3);
    tgemm_kernel<<<gqkv, 256, GEMM_SMEM>>>(bq, bk, bv, 0, n, qscale);

    zero_cnt_kernel<<<(n + 255) / 256, 256>>>(n);
    hist_kernel<<<(E + 255) / 256, 256>>>(dst, E);
    scan_kernel<<<1, 1024>>>(n);
    scatter_kernel<<<(E + 255) / 256, 256>>>(dst, E);

    attn_kernel<<<n, 128>>>(src, n);

    dim3 go(4, (n + 127) / 128, 1);
    tgemm_kernel<<<go, 256, GEMM_SMEM>>>(bo, bo, bo, 3, n, 1.f);
    expmap_kernel<<<n, 128>>>(out, n);
}

// round 6
// speedup vs baseline: 3.1805x; 1.1234x over previous
#include <cuda_runtime.h>
#include <math.h>
#include <stdint.h>

#define D 512
#define NMAX 20000
#define EMAX 320000

// ---------------- scratch (device globals: allocation-free) ----------------
__device__ float g_t[NMAX * D];      // tangent vectors, tf32-rounded
__device__ float g_q[NMAX * D];      // q ; later reused as h
__device__ float g_k[NMAX * D];
__device__ float g_v[NMAX * D];
__device__ float g_attn[NMAX * D];   // tf32-rounded at write
__device__ float g_Wc[4 * D * D];    // tf32-rounded weight copies (q,k,v,o)
__device__ float g_scores[EMAX];
__device__ int   g_cnt[NMAX];
__device__ int   g_off[NMAX + 1];
__device__ int   g_cur[NMAX];
__device__ int   g_srcs[EMAX];       // src node id in CSR order (no eid hop)

__device__ __forceinline__ float f2tf32(float x) {
    uint32_t u;
    asm("cvt.rna.tf32.f32 %0, %1;" : "=r"(u) : "f"(x));
    return __uint_as_float(u);
}

__device__ __forceinline__ void cp_async16(void* sptr, const void* gptr, bool pred) {
    uint32_t sa = (uint32_t)__cvta_generic_to_shared(sptr);
    int sz = pred ? 16 : 0;
    asm volatile("cp.async.cg.shared.global [%0], [%1], 16, %2;\n"
                 :: "r"(sa), "l"(gptr), "r"(sz));
}

// ---------------- W conversion (tf32 round, once per call) -----------------
__global__ void convw_kernel(const float* __restrict__ Wq, const float* __restrict__ Wk,
                             const float* __restrict__ Wv, const float* __restrict__ Wo) {
    int i = blockIdx.x * blockDim.x + threadIdx.x;   // float4 index
    int total = 4 * D * D / 4;
    if (i >= total) return;
    int which = i / (D * D / 4);
    int off = i - which * (D * D / 4);
    const float* src = (which == 0) ? Wq : (which == 1) ? Wk : (which == 2) ? Wv : Wo;
    float4 v = ((const float4*)src)[off];
    v.x = f2tf32(v.x); v.y = f2tf32(v.y); v.z = f2tf32(v.z); v.w = f2tf32(v.w);
    ((float4*)g_Wc)[i] = v;
}

// ---------------- logmap0 (writes tf32-rounded tangent) --------------------
__global__ void logmap_kernel(const float* __restrict__ x, int n) {
    int row = blockIdx.x;
    if (row >= n) return;
    const float4* xr = (const float4*)(x + (size_t)row * D);
    float4 xv = xr[threadIdx.x];
    float ss = xv.x * xv.x + xv.y * xv.y + xv.z * xv.z + xv.w * xv.w;
    for (int o = 16; o > 0; o >>= 1) ss += __shfl_down_sync(0xffffffffu, ss, o);
    __shared__ float sred[4];
    int lane = threadIdx.x & 31, w = threadIdx.x >> 5;
    if (lane == 0) sred[w] = ss;
    __syncthreads();
    float tot = sred[0] + sred[1] + sred[2] + sred[3];
    float nrm = sqrtf(tot);
    float nc = fminf(fmaxf(nrm, 1e-7f), 1.f - 1e-6f);
    float fac = atanhf(nc) / nc;
    float4 o4;
    o4.x = f2tf32(fac * xv.x); o4.y = f2tf32(fac * xv.y);
    o4.z = f2tf32(fac * xv.z); o4.w = f2tf32(fac * xv.w);
    ((float4*)(g_t + (size_t)row * D))[threadIdx.x] = o4;
}

// ---------------- expmap0 (reads g_q as h, writes output) ------------------
__global__ void expmap_kernel(float* __restrict__ out, int n) {
    int row = blockIdx.x;
    if (row >= n) return;
    const float4* hr = (const float4*)(g_q + (size_t)row * D);
    float4 hv = hr[threadIdx.x];
    float ss = hv.x * hv.x + hv.y * hv.y + hv.z * hv.z + hv.w * hv.w;
    for (int o = 16; o > 0; o >>= 1) ss += __shfl_down_sync(0xffffffffu, ss, o);
    __shared__ float sred[4];
    int lane = threadIdx.x & 31, w = threadIdx.x >> 5;
    if (lane == 0) sred[w] = ss;
    __syncthreads();
    float tot = sred[0] + sred[1] + sred[2] + sred[3];
    float nrm = sqrtf(tot);
    float nc = fmaxf(nrm, 1e-7f);
    float fac = tanhf(nc) / nc;
    float4 o4;
    o4.x = fac * hv.x; o4.y = fac * hv.y; o4.z = fac * hv.z; o4.w = fac * hv.w;
    ((float4*)(out + (size_t)row * D))[threadIdx.x] = o4;
}

// ---------------- TF32 tensor-core GEMM (cp.async double-buffered) ---------
//   C[M,512] = (A[M,512] @ W[512,512]^T + bias) * scale
// sel = sel_base + blockIdx.z : 0->q 1->k 2->v (A=g_t), 3->h (A=g_attn, C=g_q)
// SM_STRIDE 36: fragment LDS bank = (4g+tg+c) mod 32 = (lane+c) mod 32
//  -> conflict-free; 36*4=144 bytes keeps float4/cp.async 16B alignment.
#define SM_STRIDE 36
#define TILE_FLOATS (128 * SM_STRIDE)
#define GEMM_SMEM (4 * TILE_FLOATS * 4)   // 2 bufs x (A+W) x 128x36 floats

__global__ __launch_bounds__(256, 2)
void tgemm_kernel(const float* __restrict__ b0, const float* __restrict__ b1,
                  const float* __restrict__ b2, int sel_base, int M, float qscale) {
    extern __shared__ float smem[];
    int sel = sel_base + blockIdx.z;
    const float* __restrict__ A = (sel == 3) ? g_attn : g_t;
    const float* __restrict__ W = g_Wc + (size_t)sel * D * D;
    float* __restrict__ C = (sel == 1) ? g_k : (sel == 2) ? g_v : g_q;
    const float* __restrict__ bias = (blockIdx.z == 0) ? b0 : (blockIdx.z == 1) ? b1 : b2;
    float scale = (sel == 0) ? qscale : 1.f;

    int bm = blockIdx.y * 128, bn = blockIdx.x * 128;
    int tid = threadIdx.x;
    int lane = tid & 31, warp = tid >> 5;
    int wm = (warp >> 2) * 64;
    int wn = (warp & 3) * 32;
    int g = lane >> 2, tg = lane & 3;
    int lrow = tid >> 3, lcol = (tid & 7) << 2;

    float acc[4][4][4];
#pragma unroll
    for (int mt = 0; mt < 4; mt++)
#pragma unroll
        for (int nt = 0; nt < 4; nt++)
#pragma unroll
            for (int i = 0; i < 4; i++) acc[mt][nt][i] = 0.f;

    auto prefetch = [&](int it) {
        float* As = smem + (it & 1) * 2 * TILE_FLOATS;
        float* Ws = As + TILE_FLOATS;
        int k0 = it * 32;
#pragma unroll
        for (int i = 0; i < 4; i++) {
            int row = lrow + i * 32;
            int ga = bm + row;
            cp_async16(&As[row * SM_STRIDE + lcol],
                       A + (size_t)ga * D + k0 + lcol, ga < M);
            cp_async16(&Ws[row * SM_STRIDE + lcol],
                       W + (size_t)(bn + row) * D + k0 + lcol, true);
        }
        asm volatile("cp.async.commit_group;\n" ::);
    };

    prefetch(0);

    for (int it = 0; it < 16; it++) {
        // Issue next tile FIRST so wait_group 1 guarantees tile `it` landed.
        if (it + 1 < 16) {
            prefetch(it + 1);
            asm volatile("cp.async.wait_group 1;\n" ::);
        } else {
            asm volatile("cp.async.wait_group 0;\n" ::);
        }
        __syncthreads();

        const float* As = smem + (it & 1) * 2 * TILE_FLOATS;
        const float* Ws = As + TILE_FLOATS;

#pragma unroll
        for (int ks = 0; ks < 4; ks++) {
            int kb = ks * 8;
            uint32_t af[4][4], bf[4][2];
#pragma unroll
            for (int mt = 0; mt < 4; mt++) {
                int r = wm + mt * 16 + g;
                af[mt][0] = __float_as_uint(As[r * SM_STRIDE + kb + tg]);
                af[mt][1] = __float_as_uint(As[(r + 8) * SM_STRIDE + kb + tg]);
                af[mt][2] = __float_as_uint(As[r * SM_STRIDE + kb + tg + 4]);
                af[mt][3] = __float_as_uint(As[(r + 8) * SM_STRIDE + kb + tg + 4]);
            }
#pragma unroll
            for (int nt = 0; nt < 4; nt++) {
                int r = wn + nt * 8 + g;
                bf[nt][0] = __float_as_uint(Ws[r * SM_STRIDE + kb + tg]);
                bf[nt][1] = __float_as_uint(Ws[r * SM_STRIDE + kb + tg + 4]);
            }
#pragma unroll
            for (int mt = 0; mt < 4; mt++)
#pragma unroll
                for (int nt = 0; nt < 4; nt++) {
                    asm volatile(
                        "mma.sync.aligned.m16n8k8.row.col.f32.tf32.tf32.f32 "
                        "{%0,%1,%2,%3}, {%4,%5,%6,%7}, {%8,%9}, {%0,%1,%2,%3};"
                        : "+f"(acc[mt][nt][0]), "+f"(acc[mt][nt][1]),
                          "+f"(acc[mt][nt][2]), "+f"(acc[mt][nt][3])
                        : "r"(af[mt][0]), "r"(af[mt][1]),
                          "r"(af[mt][2]), "r"(af[mt][3]),
                          "r"(bf[nt][0]), "r"(bf[nt][1]));
                }
        }
        __syncthreads();
    }

#pragma unroll
    for (int mt = 0; mt < 4; mt++) {
        int row0 = bm + wm + mt * 16 + g;
#pragma unroll
        for (int nt = 0; nt < 4; nt++) {
            int col = bn + wn + nt * 8 + tg * 2;
            float b0v = bias[col], b1v = bias[col + 1];
            if (row0 < M) {
                float2 o;
                o.x = (acc[mt][nt][0] + b0v) * scale;
                o.y = (acc[mt][nt][1] + b1v) * scale;
                *(float2*)(C + (size_t)row0 * D + col) = o;
            }
            if (row0 + 8 < M) {
                float2 o;
                o.x = (acc[mt][nt][2] + b0v) * scale;
                o.y = (acc[mt][nt][3] + b1v) * scale;
                *(float2*)(C + (size_t)(row0 + 8) * D + col) = o;
            }
        }
    }
}

// ---------------- CSR build (by dst) ----------------
__global__ void zero_cnt_kernel(int n) {
    int i = blockIdx.x * blockDim.x + threadIdx.x;
    if (i < n) g_cnt[i] = 0;
}
__global__ void hist_kernel(const int* __restrict__ dst, int E) {
    int i = blockIdx.x * blockDim.x + threadIdx.x;
    if (i < E) atomicAdd(&g_cnt[dst[i]], 1);
}
__global__ void scan_kernel(int n) {
    __shared__ int sdata[1024];
    __shared__ int carry_s;
    int t = threadIdx.x;
    if (t == 0) carry_s = 0;
    __syncthreads();
    for (int base = 0; base < n; base += 1024) {
        int idx = base + t;
        int v = (idx < n) ? g_cnt[idx] : 0;
        sdata[t] = v;
        __syncthreads();
        for (int off = 1; off < 1024; off <<= 1) {
            int tmp = (t >= off) ? sdata[t - off] : 0;
            __syncthreads();
            sdata[t] += tmp;
            __syncthreads();
        }
        int incl = sdata[t];
        int carry = carry_s;
        if (idx < n) {
            int excl = carry + incl - v;
            g_off[idx] = excl;
            g_cur[idx] = excl;
        }
        __syncthreads();
        if (t == 1023) carry_s = carry + incl;
        __syncthreads();
    }
    if (t == 0) g_off[n] = carry_s;
}
// scatter: store src VALUE in CSR slot (removes the eid indirection hop)
__global__ void scatter_kernel(const int* __restrict__ src,
                               const int* __restrict__ dst, int E) {
    int i = blockIdx.x * blockDim.x + threadIdx.x;
    if (i < E) {
        int p = atomicAdd(&g_cur[dst[i]], 1);
        g_srcs[p] = src[i];
    }
}

// ---------------- fused per-dst attention ----------------------------------
__global__ void attn_kernel(int n) {
    int dnode = blockIdx.x;
    if (dnode >= n) return;
    int beg = g_off[dnode], end = g_off[dnode + 1];
    __shared__ float4 qs[D / 4];
    __shared__ float sred[4];
    __shared__ float s_m, s_inv;
    __shared__ int   s_src[128];
    __shared__ float s_al[128];
    int tid = threadIdx.x, lane = tid & 31, w = tid >> 5;

    qs[tid] = ((const float4*)(g_q + (size_t)dnode * D))[tid];
    __syncthreads();

    // pass 1: scores + block max (warp per edge, float4 dots, direct src)
    float wmax = -3.4e38f;
    for (int e = beg + w; e < end; e += 4) {
        int s = g_srcs[e];
        const float4* kr = (const float4*)(g_k + (size_t)s * D);
        float acc = 0.f;
#pragma unroll
        for (int i = 0; i < 4; i++) {
            float4 kv = kr[lane + 32 * i];
            float4 qv = qs[lane + 32 * i];
            acc += kv.x * qv.x + kv.y * qv.y + kv.z * qv.z + kv.w * qv.w;
        }
        for (int o = 16; o > 0; o >>= 1) acc += __shfl_down_sync(0xffffffffu, acc, o);
        if (lane == 0) {
            g_scores[e] = acc;
            wmax = fmaxf(wmax, acc);
        }
    }
    if (lane == 0) sred[w] = wmax;
    __syncthreads();
    if (tid == 0)
        s_m = fmaxf(fmaxf(sred[0], sred[1]), fmaxf(sred[2], sred[3]));
    __syncthreads();
    float m = s_m;

    // pass 2: exp + denom
    float ds = 0.f;
    for (int e = beg + tid; e < end; e += 128) {
        float ex = expf(g_scores[e] - m);
        g_scores[e] = ex;
        ds += ex;
    }
    for (int o = 16; o > 0; o >>= 1) ds += __shfl_down_sync(0xffffffffu, ds, o);
    __syncthreads();
    if (lane == 0) sred[w] = ds;
    __syncthreads();
    if (tid == 0) s_inv = 1.f / (sred[0] + sred[1] + sred[2] + sred[3]);
    __syncthreads();
    float inv = s_inv;

    // pass 3: chunked smem staging of (src, alpha); v-row loads independent.
    float4 a = make_float4(0.f, 0.f, 0.f, 0.f);
    for (int c0 = beg; c0 < end; c0 += 128) {
        int cnt = min(128, end - c0);
        if (tid < cnt) {
            s_src[tid] = g_srcs[c0 + tid];
            s_al[tid] = g_scores[c0 + tid] * inv;
        }
        __syncthreads();
#pragma unroll 4
        for (int j = 0; j < cnt; j++) {
            int s = s_src[j];
            float al = s_al[j];
            float4 v4 = ((const float4*)(g_v + (size_t)s * D))[tid];
            a.x += al * v4.x; a.y += al * v4.y;
            a.z += al * v4.z; a.w += al * v4.w;
        }
        __syncthreads();
    }
    float4 o4;
    o4.x = f2tf32(a.x); o4.y = f2tf32(a.y);
    o4.z = f2tf32(a.z); o4.w = f2tf32(a.w);
    ((float4*)(g_attn + (size_t)dnode * D))[tid] = o4;
}

// ---------------- launch ----------------
extern "C" void kernel_launch(void* const* d_in, const int* in_sizes, int n_in,
                              void* d_out, int out_size) {
    const float* x  = (const float*)d_in[0];
    const int*   src = (const int*)d_in[1];
    const int*   dst = (const int*)d_in[2];
    const float* Wq = (const float*)d_in[3];
    const float* bq = (const float*)d_in[4];
    const float* Wk = (const float*)d_in[5];
    const float* bk = (const float*)d_in[6];
    const float* Wv = (const float*)d_in[7];
    const float* bv = (const float*)d_in[8];
    const float* Wo = (const float*)d_in[9];
    const float* bo = (const float*)d_in[10];
    float* out = (float*)d_out;

    int n = in_sizes[0] / D;
    int E = in_sizes[1];
    float qscale = 1.f / sqrtf((float)D);

    cudaFuncSetAttribute(tgemm_kernel,
                         cudaFuncAttributeMaxDynamicSharedMemorySize, GEMM_SMEM);

    convw_kernel<<<(4 * D * D / 4 + 255) / 256, 256>>>(Wq, Wk, Wv, Wo);
    logmap_kernel<<<n, 128>>>(x, n);

    dim3 gqkv(4, (n + 127) / 128, 3);
    tgemm_kernel<<<gqkv, 256, GEMM_SMEM>>>(bq, bk, bv, 0, n, qscale);

    zero_cnt_kernel<<<(n + 255) / 256, 256>>>(n);
    hist_kernel<<<(E + 255) / 256, 256>>>(dst, E);
    scan_kernel<<<1, 1024>>>(n);
    scatter_kernel<<<(E + 255) / 256, 256>>>(src, dst, E);

    attn_kernel<<<n, 128>>>(n);

    dim3 go(4, (n + 127) / 128, 1);
    tgemm_kernel<<<go, 256, GEMM_SMEM>>>(bo, bo, bo, 3, n, 1.f);
    expmap_kernel<<<n, 128>>>(out, n);
}

// round 7
// speedup vs baseline: 3.2672x; 1.0272x over previous
#include <cuda_runtime.h>
#include <math.h>
#include <stdint.h>

#define D 512
#define NMAX 20000
#define EMAX 320000

// ---------------- scratch (device globals: allocation-free) ----------------
__device__ float g_t[NMAX * D];      // tangent vectors, tf32-rounded
__device__ float g_q[NMAX * D];      // q ; later reused as h
__device__ float g_k[NMAX * D];
__device__ float g_v[NMAX * D];
__device__ float g_attn[NMAX * D];   // tf32-rounded at write
__device__ float g_Wc[4 * D * D];    // tf32-rounded weight copies (q,k,v,o)
__device__ float g_scores[EMAX];
__device__ int   g_cnt[NMAX];
__device__ int   g_off[NMAX + 1];
__device__ int   g_cur[NMAX];
__device__ int   g_srcs[EMAX];       // src node id in CSR order

__device__ __forceinline__ float f2tf32(float x) {
    uint32_t u;
    asm("cvt.rna.tf32.f32 %0, %1;" : "=r"(u) : "f"(x));
    return __uint_as_float(u);
}

__device__ __forceinline__ void cp_async16(void* sptr, const void* gptr, bool pred) {
    uint32_t sa = (uint32_t)__cvta_generic_to_shared(sptr);
    int sz = pred ? 16 : 0;
    asm volatile("cp.async.cg.shared.global [%0], [%1], 16, %2;\n"
                 :: "r"(sa), "l"(gptr), "r"(sz));
}

// ---------------- W conversion (tf32 round, once per call) -----------------
__global__ void convw_kernel(const float* __restrict__ Wq, const float* __restrict__ Wk,
                             const float* __restrict__ Wv, const float* __restrict__ Wo) {
    int i = blockIdx.x * blockDim.x + threadIdx.x;   // float4 index
    int total = 4 * D * D / 4;
    if (i >= total) return;
    int which = i / (D * D / 4);
    int off = i - which * (D * D / 4);
    const float* src = (which == 0) ? Wq : (which == 1) ? Wk : (which == 2) ? Wv : Wo;
    float4 v = ((const float4*)src)[off];
    v.x = f2tf32(v.x); v.y = f2tf32(v.y); v.z = f2tf32(v.z); v.w = f2tf32(v.w);
    ((float4*)g_Wc)[i] = v;
}

// ---------------- logmap0 (writes tf32-rounded tangent) --------------------
__global__ void logmap_kernel(const float* __restrict__ x, int n) {
    int row = blockIdx.x;
    if (row >= n) return;
    const float4* xr = (const float4*)(x + (size_t)row * D);
    float4 xv = xr[threadIdx.x];
    float ss = xv.x * xv.x + xv.y * xv.y + xv.z * xv.z + xv.w * xv.w;
    for (int o = 16; o > 0; o >>= 1) ss += __shfl_down_sync(0xffffffffu, ss, o);
    __shared__ float sred[4];
    int lane = threadIdx.x & 31, w = threadIdx.x >> 5;
    if (lane == 0) sred[w] = ss;
    __syncthreads();
    float tot = sred[0] + sred[1] + sred[2] + sred[3];
    float nrm = sqrtf(tot);
    float nc = fminf(fmaxf(nrm, 1e-7f), 1.f - 1e-6f);
    float fac = atanhf(nc) / nc;
    float4 o4;
    o4.x = f2tf32(fac * xv.x); o4.y = f2tf32(fac * xv.y);
    o4.z = f2tf32(fac * xv.z); o4.w = f2tf32(fac * xv.w);
    ((float4*)(g_t + (size_t)row * D))[threadIdx.x] = o4;
}

// ---------------- expmap0 (reads g_q as h, writes output) ------------------
__global__ void expmap_kernel(float* __restrict__ out, int n) {
    int row = blockIdx.x;
    if (row >= n) return;
    const float4* hr = (const float4*)(g_q + (size_t)row * D);
    float4 hv = hr[threadIdx.x];
    float ss = hv.x * hv.x + hv.y * hv.y + hv.z * hv.z + hv.w * hv.w;
    for (int o = 16; o > 0; o >>= 1) ss += __shfl_down_sync(0xffffffffu, ss, o);
    __shared__ float sred[4];
    int lane = threadIdx.x & 31, w = threadIdx.x >> 5;
    if (lane == 0) sred[w] = ss;
    __syncthreads();
    float tot = sred[0] + sred[1] + sred[2] + sred[3];
    float nrm = sqrtf(tot);
    float nc = fmaxf(nrm, 1e-7f);
    float fac = tanhf(nc) / nc;
    float4 o4;
    o4.x = fac * hv.x; o4.y = fac * hv.y; o4.z = fac * hv.z; o4.w = fac * hv.w;
    ((float4*)(out + (size_t)row * D))[threadIdx.x] = o4;
}

// ---------------- TF32 tensor-core GEMM (3-stage cp.async pipeline) --------
//   C[M,512] = (A[M,512] @ W[512,512]^T + bias) * scale
// sel = sel_base + blockIdx.z : 0->q 1->k 2->v (A=g_t), 3->h (A=g_attn, C=g_q)
// SM_STRIDE 36 -> conflict-free fragment LDS; 3 stages keep 2 tiles in flight
// so the ~600cyc L2 load latency is hidden behind ~512cyc of MMA work.
#define SM_STRIDE 36
#define TILE_FLOATS (128 * SM_STRIDE)
#define NSTAGE 3
#define GEMM_SMEM (NSTAGE * 2 * TILE_FLOATS * 4)   // 3 stages x (A+W) x 128x36

__global__ __launch_bounds__(256, 2)
void tgemm_kernel(const float* __restrict__ b0, const float* __restrict__ b1,
                  const float* __restrict__ b2, int sel_base, int M, float qscale) {
    extern __shared__ float smem[];
    int sel = sel_base + blockIdx.z;
    const float* __restrict__ A = (sel == 3) ? g_attn : g_t;
    const float* __restrict__ W = g_Wc + (size_t)sel * D * D;
    float* __restrict__ C = (sel == 1) ? g_k : (sel == 2) ? g_v : g_q;
    const float* __restrict__ bias = (blockIdx.z == 0) ? b0 : (blockIdx.z == 1) ? b1 : b2;
    float scale = (sel == 0) ? qscale : 1.f;

    int bm = blockIdx.y * 128, bn = blockIdx.x * 128;
    int tid = threadIdx.x;
    int lane = tid & 31, warp = tid >> 5;
    int wm = (warp >> 2) * 64;
    int wn = (warp & 3) * 32;
    int g = lane >> 2, tg = lane & 3;
    int lrow = tid >> 3, lcol = (tid & 7) << 2;

    float acc[4][4][4];
#pragma unroll
    for (int mt = 0; mt < 4; mt++)
#pragma unroll
        for (int nt = 0; nt < 4; nt++)
#pragma unroll
            for (int i = 0; i < 4; i++) acc[mt][nt][i] = 0.f;

    auto prefetch = [&](int it) {
        float* As = smem + (it % NSTAGE) * 2 * TILE_FLOATS;
        float* Ws = As + TILE_FLOATS;
        int k0 = it * 32;
#pragma unroll
        for (int i = 0; i < 4; i++) {
            int row = lrow + i * 32;
            int ga = bm + row;
            cp_async16(&As[row * SM_STRIDE + lcol],
                       A + (size_t)ga * D + k0 + lcol, ga < M);
            cp_async16(&Ws[row * SM_STRIDE + lcol],
                       W + (size_t)(bn + row) * D + k0 + lcol, true);
        }
        asm volatile("cp.async.commit_group;\n" ::);
    };

    prefetch(0);
    prefetch(1);

    for (int it = 0; it < 16; it++) {
        // prefetch(it+2) targets buf (it+2)%3 == (it-1)%3, whose compute
        // finished at iter it-1 and was fenced by its trailing barrier.
        if (it + 2 < 16) {
            prefetch(it + 2);
            asm volatile("cp.async.wait_group 2;\n" ::);   // tile `it` landed
        } else if (it + 1 < 16) {
            asm volatile("cp.async.wait_group 1;\n" ::);   // it == 14
        } else {
            asm volatile("cp.async.wait_group 0;\n" ::);   // it == 15
        }
        __syncthreads();

        const float* As = smem + (it % NSTAGE) * 2 * TILE_FLOATS;
        const float* Ws = As + TILE_FLOATS;

#pragma unroll
        for (int ks = 0; ks < 4; ks++) {
            int kb = ks * 8;
            uint32_t af[4][4], bf[4][2];
#pragma unroll
            for (int mt = 0; mt < 4; mt++) {
                int r = wm + mt * 16 + g;
                af[mt][0] = __float_as_uint(As[r * SM_STRIDE + kb + tg]);
                af[mt][1] = __float_as_uint(As[(r + 8) * SM_STRIDE + kb + tg]);
                af[mt][2] = __float_as_uint(As[r * SM_STRIDE + kb + tg + 4]);
                af[mt][3] = __float_as_uint(As[(r + 8) * SM_STRIDE + kb + tg + 4]);
            }
#pragma unroll
            for (int nt = 0; nt < 4; nt++) {
                int r = wn + nt * 8 + g;
                bf[nt][0] = __float_as_uint(Ws[r * SM_STRIDE + kb + tg]);
                bf[nt][1] = __float_as_uint(Ws[r * SM_STRIDE + kb + tg + 4]);
            }
#pragma unroll
            for (int mt = 0; mt < 4; mt++)
#pragma unroll
                for (int nt = 0; nt < 4; nt++) {
                    asm volatile(
                        "mma.sync.aligned.m16n8k8.row.col.f32.tf32.tf32.f32 "
                        "{%0,%1,%2,%3}, {%4,%5,%6,%7}, {%8,%9}, {%0,%1,%2,%3};"
                        : "+f"(acc[mt][nt][0]), "+f"(acc[mt][nt][1]),
                          "+f"(acc[mt][nt][2]), "+f"(acc[mt][nt][3])
                        : "r"(af[mt][0]), "r"(af[mt][1]),
                          "r"(af[mt][2]), "r"(af[mt][3]),
                          "r"(bf[nt][0]), "r"(bf[nt][1]));
                }
        }
        __syncthreads();
    }

#pragma unroll
    for (int mt = 0; mt < 4; mt++) {
        int row0 = bm + wm + mt * 16 + g;
#pragma unroll
        for (int nt = 0; nt < 4; nt++) {
            int col = bn + wn + nt * 8 + tg * 2;
            float b0v = bias[col], b1v = bias[col + 1];
            if (row0 < M) {
                float2 o;
                o.x = (acc[mt][nt][0] + b0v) * scale;
                o.y = (acc[mt][nt][1] + b1v) * scale;
                *(float2*)(C + (size_t)row0 * D + col) = o;
            }
            if (row0 + 8 < M) {
                float2 o;
                o.x = (acc[mt][nt][2] + b0v) * scale;
                o.y = (acc[mt][nt][3] + b1v) * scale;
                *(float2*)(C + (size_t)(row0 + 8) * D + col) = o;
            }
        }
    }
}

// ---------------- CSR build (by dst) ----------------
__global__ void zero_cnt_kernel(int n) {
    int i = blockIdx.x * blockDim.x + threadIdx.x;
    if (i < n) g_cnt[i] = 0;
}
__global__ void hist_kernel(const int* __restrict__ dst, int E) {
    int i = blockIdx.x * blockDim.x + threadIdx.x;
    if (i < E) atomicAdd(&g_cnt[dst[i]], 1);
}
__global__ void scan_kernel(int n) {
    __shared__ int sdata[1024];
    __shared__ int carry_s;
    int t = threadIdx.x;
    if (t == 0) carry_s = 0;
    __syncthreads();
    for (int base = 0; base < n; base += 1024) {
        int idx = base + t;
        int v = (idx < n) ? g_cnt[idx] : 0;
        sdata[t] = v;
        __syncthreads();
        for (int off = 1; off < 1024; off <<= 1) {
            int tmp = (t >= off) ? sdata[t - off] : 0;
            __syncthreads();
            sdata[t] += tmp;
            __syncthreads();
        }
        int incl = sdata[t];
        int carry = carry_s;
        if (idx < n) {
            int excl = carry + incl - v;
            g_off[idx] = excl;
            g_cur[idx] = excl;
        }
        __syncthreads();
        if (t == 1023) carry_s = carry + incl;
        __syncthreads();
    }
    if (t == 0) g_off[n] = carry_s;
}
__global__ void scatter_kernel(const int* __restrict__ src,
                               const int* __restrict__ dst, int E) {
    int i = blockIdx.x * blockDim.x + threadIdx.x;
    if (i < E) {
        int p = atomicAdd(&g_cur[dst[i]], 1);
        g_srcs[p] = src[i];
    }
}

// ---------------- fused per-dst attention ----------------------------------
__global__ void attn_kernel(int n) {
    int dnode = blockIdx.x;
    if (dnode >= n) return;
    int beg = g_off[dnode], end = g_off[dnode + 1];
    __shared__ float4 qs[D / 4];
    __shared__ float sred[4];
    __shared__ float s_m, s_inv;
    __shared__ int   s_src[128];
    __shared__ float s_al[128];
    int tid = threadIdx.x, lane = tid & 31, w = tid >> 5;

    qs[tid] = ((const float4*)(g_q + (size_t)dnode * D))[tid];
    __syncthreads();

    // pass 1: scores + block max (warp per edge, float4 dots)
    float wmax = -3.4e38f;
    for (int e = beg + w; e < end; e += 4) {
        int s = g_srcs[e];
        const float4* kr = (const float4*)(g_k + (size_t)s * D);
        float acc = 0.f;
#pragma unroll
        for (int i = 0; i < 4; i++) {
            float4 kv = kr[lane + 32 * i];
            float4 qv = qs[lane + 32 * i];
            acc += kv.x * qv.x + kv.y * qv.y + kv.z * qv.z + kv.w * qv.w;
        }
        for (int o = 16; o > 0; o >>= 1) acc += __shfl_down_sync(0xffffffffu, acc, o);
        if (lane == 0) {
            g_scores[e] = acc;
            wmax = fmaxf(wmax, acc);
        }
    }
    if (lane == 0) sred[w] = wmax;
    __syncthreads();
    if (tid == 0)
        s_m = fmaxf(fmaxf(sred[0], sred[1]), fmaxf(sred[2], sred[3]));
    __syncthreads();
    float m = s_m;

    // pass 2: exp + denom
    float ds = 0.f;
    for (int e = beg + tid; e < end; e += 128) {
        float ex = expf(g_scores[e] - m);
        g_scores[e] = ex;
        ds += ex;
    }
    for (int o = 16; o > 0; o >>= 1) ds += __shfl_down_sync(0xffffffffu, ds, o);
    __syncthreads();
    if (lane == 0) sred[w] = ds;
    __syncthreads();
    if (tid == 0) s_inv = 1.f / (sred[0] + sred[1] + sred[2] + sred[3]);
    __syncthreads();
    float inv = s_inv;

    // pass 3: chunked smem staging of (src, alpha); v-row loads independent
    float4 a = make_float4(0.f, 0.f, 0.f, 0.f);
    for (int c0 = beg; c0 < end; c0 += 128) {
        int cnt = min(128, end - c0);
        if (tid < cnt) {
            s_src[tid] = g_srcs[c0 + tid];
            s_al[tid] = g_scores[c0 + tid] * inv;
        }
        __syncthreads();
#pragma unroll 4
        for (int j = 0; j < cnt; j++) {
            int s = s_src[j];
            float al = s_al[j];
            float4 v4 = ((const float4*)(g_v + (size_t)s * D))[tid];
            a.x += al * v4.x; a.y += al * v4.y;
            a.z += al * v4.z; a.w += al * v4.w;
        }
        __syncthreads();
    }
    float4 o4;
    o4.x = f2tf32(a.x); o4.y = f2tf32(a.y);
    o4.z = f2tf32(a.z); o4.w = f2tf32(a.w);
    ((float4*)(g_attn + (size_t)dnode * D))[tid] = o4;
}

// ---------------- launch ----------------
extern "C" void kernel_launch(void* const* d_in, const int* in_sizes, int n_in,
                              void* d_out, int out_size) {
    const float* x  = (const float*)d_in[0];
    const int*   src = (const int*)d_in[1];
    const int*   dst = (const int*)d_in[2];
    const float* Wq = (const float*)d_in[3];
    const float* bq = (const float*)d_in[4];
    const float* Wk = (const float*)d_in[5];
    const float* bk = (const float*)d_in[6];
    const float* Wv = (const float*)d_in[7];
    const float* bv = (const float*)d_in[8];
    const float* Wo = (const float*)d_in[9];
    const float* bo = (const float*)d_in[10];
    float* out = (float*)d_out;

    int n = in_sizes[0] / D;
    int E = in_sizes[1];
    float qscale = 1.f / sqrtf((float)D);

    // side stream + events (created once, before any capture)
    static cudaStream_t s2 = nullptr;
    static cudaEvent_t evFork = nullptr, evW = nullptr, evJoin = nullptr;
    if (!s2) {
        cudaStreamCreateWithFlags(&s2, cudaStreamNonBlocking);
        cudaEventCreateWithFlags(&evFork, cudaEventDisableTiming);
        cudaEventCreateWithFlags(&evW, cudaEventDisableTiming);
        cudaEventCreateWithFlags(&evJoin, cudaEventDisableTiming);
    }

    cudaFuncSetAttribute(tgemm_kernel,
                         cudaFuncAttributeMaxDynamicSharedMemorySize, GEMM_SMEM);

    // fork: side stream does convw + CSR build while main does logmap + GEMMs
    cudaEventRecord(evFork, 0);
    cudaStreamWaitEvent(s2, evFork, 0);

    convw_kernel<<<(4 * D * D / 4 + 255) / 256, 256, 0, s2>>>(Wq, Wk, Wv, Wo);
    cudaEventRecord(evW, s2);
    zero_cnt_kernel<<<(n + 255) / 256, 256, 0, s2>>>(n);
    hist_kernel<<<(E + 255) / 256, 256, 0, s2>>>(dst, E);
    scan_kernel<<<1, 1024, 0, s2>>>(n);
    scatter_kernel<<<(E + 255) / 256, 256, 0, s2>>>(src, dst, E);
    cudaEventRecord(evJoin, s2);

    logmap_kernel<<<n, 128>>>(x, n);
    cudaStreamWaitEvent(0, evW, 0);     // weights ready for GEMM

    dim3 gqkv(4, (n + 127) / 128, 3);
    tgemm_kernel<<<gqkv, 256, GEMM_SMEM>>>(bq, bk, bv, 0, n, qscale);

    cudaStreamWaitEvent(0, evJoin, 0);  // CSR ready for attention
    attn_kernel<<<n, 128>>>(n);

    dim3 go(4, (n + 127) / 128, 1);
    tgemm_kernel<<<go, 256, GEMM_SMEM>>>(bo, bo, bo, 3, n, 1.f);
    expmap_kernel<<<n, 128>>>(out, n);
}